// round 2
// baseline (speedup 1.0000x reference)
#include <cuda_runtime.h>
#include <cstdint>

#define NNODES 100000
#define NEDGES 3200000
#define HDIM   64
#define FIN    100
#define CDIM   18

// ---------------- scratch (device globals — no allocation allowed) ----------
__device__ float g_h[(size_t)NNODES * HDIM];      // current node features
__device__ float g_mean[(size_t)NNODES * HDIM];   // aggregated neighbor mean
__device__ int   g_deg[NNODES];                   // in-degree histogram
__device__ int   g_off[NNODES + 1];               // CSR offsets (by dst)
__device__ int   g_cur[NNODES];                   // scatter cursors
__device__ int   g_src[NEDGES];                   // CSR: src per slot
__device__ float g_w[NEDGES];                     // CSR: edge weight per slot

__device__ __forceinline__ int clampi(int v, int lo, int hi) {
    return v < lo ? lo : (v > hi ? hi : v);
}

// ---------------- embedding: h = relu(x @ W + b) ----------------------------
__global__ __launch_bounds__(256) void embed_kernel(
    const float* __restrict__ x, const float* __restrict__ W,
    const float* __restrict__ b)
{
    __shared__ float sW[FIN * HDIM];   // 25.6 KB
    __shared__ float sx[4][FIN];
    int tid = threadIdx.x;
    for (int i = tid; i < FIN * HDIM; i += 256) sW[i] = W[i];
    float bias = b[tid & 63];
    __syncthreads();

    int r = tid >> 6, c = tid & 63;
    int ntiles = NNODES / 4;
    for (int tile = blockIdx.x; tile < ntiles; tile += gridDim.x) {
        int n0 = tile * 4;
        for (int i = tid; i < 4 * FIN; i += 256) {
            int rr = i / FIN, k = i % FIN;
            sx[rr][k] = x[(size_t)(n0 + rr) * FIN + k];
        }
        __syncthreads();
        float acc = bias;
        #pragma unroll
        for (int k = 0; k < FIN; k++) acc += sx[r][k] * sW[k * HDIM + c];
        g_h[(size_t)(n0 + r) * HDIM + c] = fmaxf(acc, 0.f);
        __syncthreads();
    }
}

// ---------------- CSR build ---------------------------------------------------
__global__ void zero_deg_kernel() {
    int i = blockIdx.x * blockDim.x + threadIdx.x;
    if (i < NNODES) g_deg[i] = 0;
}

__global__ void hist_kernel(const int* __restrict__ ei) {
    int stride = gridDim.x * blockDim.x;
    for (int e = blockIdx.x * blockDim.x + threadIdx.x; e < NEDGES; e += stride) {
        int d = clampi(ei[NEDGES + e], 0, NNODES - 1);
        atomicAdd(&g_deg[d], 1);
    }
}

// single-block exclusive scan over 100K ints (98 tiles of 1024)
__global__ __launch_bounds__(1024) void scan_kernel() {
    __shared__ int wsum[32];
    int tid = threadIdx.x, lane = tid & 31, wid = tid >> 5;
    int carry = 0;
    for (int base = 0; base < NNODES; base += 1024) {
        int i = base + tid;
        int v = (i < NNODES) ? g_deg[i] : 0;
        int xval = v;
        #pragma unroll
        for (int d = 1; d < 32; d <<= 1) {
            int y = __shfl_up_sync(0xffffffffu, xval, d);
            if (lane >= d) xval += y;
        }
        if (lane == 31) wsum[wid] = xval;
        __syncthreads();
        if (wid == 0) {
            int s = wsum[lane];
            #pragma unroll
            for (int d = 1; d < 32; d <<= 1) {
                int y = __shfl_up_sync(0xffffffffu, s, d);
                if (lane >= d) s += y;
            }
            wsum[lane] = s;
        }
        __syncthreads();
        int excl = carry + (wid ? wsum[wid - 1] : 0) + (xval - v);
        if (i < NNODES) { g_off[i] = excl; g_cur[i] = excl; }
        int total = wsum[31];
        __syncthreads();
        carry += total;
    }
    if (tid == 0) g_off[NNODES] = carry;
}

__global__ void scatter_kernel(const int* __restrict__ ei,
                               const float* __restrict__ ew)
{
    int stride = gridDim.x * blockDim.x;
    for (int e = blockIdx.x * blockDim.x + threadIdx.x; e < NEDGES; e += stride) {
        int s = clampi(ei[e], 0, NNODES - 1);
        int d = clampi(ei[NEDGES + e], 0, NNODES - 1);
        int pos = atomicAdd(&g_cur[d], 1);
        if (pos >= 0 && pos < NEDGES) {
            g_src[pos] = s;
            g_w[pos]   = ew[e];
        }
    }
}

// ---------------- neighbor mean aggregation: g_mean = mean_{src->n} w*h[src] --
__global__ __launch_bounds__(256) void aggregate_kernel(int useW) {
    int gw   = (blockIdx.x * blockDim.x + threadIdx.x) >> 5;   // node = global warp
    int lane = threadIdx.x & 31;
    if (gw >= NNODES) return;
    int s = g_off[gw], e = g_off[gw + 1];
    const float2* h2 = (const float2*)g_h;
    float a0 = 0.f, a1 = 0.f;
    int i = s;
    for (; i + 4 <= e; i += 4) {
        int s0 = g_src[i], s1 = g_src[i + 1], s2 = g_src[i + 2], s3 = g_src[i + 3];
        float w0 = 1.f, w1 = 1.f, w2 = 1.f, w3 = 1.f;
        if (useW) { w0 = g_w[i]; w1 = g_w[i + 1]; w2 = g_w[i + 2]; w3 = g_w[i + 3]; }
        float2 v0 = h2[(size_t)s0 * 32 + lane];
        float2 v1 = h2[(size_t)s1 * 32 + lane];
        float2 v2 = h2[(size_t)s2 * 32 + lane];
        float2 v3 = h2[(size_t)s3 * 32 + lane];
        a0 += w0 * v0.x + w1 * v1.x + w2 * v2.x + w3 * v3.x;
        a1 += w0 * v0.y + w1 * v1.y + w2 * v2.y + w3 * v3.y;
    }
    for (; i < e; i++) {
        float w = useW ? g_w[i] : 1.f;
        float2 v = h2[(size_t)g_src[i] * 32 + lane];
        a0 += w * v.x; a1 += w * v.y;
    }
    float inv = 1.f / fmaxf((float)(e - s), 1.f);
    ((float2*)g_mean)[(size_t)gw * 32 + lane] = make_float2(a0 * inv, a1 * inv);
}

// ---------------- middle layers: h = relu(normalize(mean@Wl + bl + h@Wr)) ----
__global__ __launch_bounds__(256) void sage_mid_kernel(
    const float* __restrict__ Wl, const float* __restrict__ bl,
    const float* __restrict__ Wr)
{
    __shared__ float sWl[HDIM * HDIM], sWr[HDIM * HDIM], sb[HDIM];
    __shared__ float sm[4][HDIM], sh[4][HDIM];
    __shared__ float rp[4][2];
    int tid = threadIdx.x;
    for (int i = tid; i < HDIM * HDIM; i += 256) { sWl[i] = Wl[i]; sWr[i] = Wr[i]; }
    if (tid < HDIM) sb[tid] = bl[tid];
    __syncthreads();

    int r = tid >> 6, c = tid & 63;
    int lane = tid & 31, half = c >> 5;
    int ntiles = NNODES / 4;
    for (int tile = blockIdx.x; tile < ntiles; tile += gridDim.x) {
        int n0 = tile * 4;
        {
            int rr = tid >> 6, k = tid & 63;
            sm[rr][k] = g_mean[(size_t)(n0 + rr) * HDIM + k];
            sh[rr][k] = g_h  [(size_t)(n0 + rr) * HDIM + k];
        }
        __syncthreads();
        float acc = sb[c];
        #pragma unroll
        for (int k = 0; k < HDIM; k++)
            acc += sm[r][k] * sWl[k * HDIM + c] + sh[r][k] * sWr[k * HDIM + c];
        float sq = acc * acc;
        #pragma unroll
        for (int d = 16; d; d >>= 1) sq += __shfl_xor_sync(0xffffffffu, sq, d);
        if (lane == 0) rp[r][half] = sq;
        __syncthreads();
        float scale = 1.f / fmaxf(sqrtf(rp[r][0] + rp[r][1]), 1e-12f);
        g_h[(size_t)(n0 + r) * HDIM + c] = fmaxf(acc * scale, 0.f);
        __syncthreads();
    }
}

// ---------------- final layer: out = normalize(mean@Wl4 + bl4 + h@Wr4) -------
__global__ __launch_bounds__(256) void sage_final_kernel(
    const float* __restrict__ Wl, const float* __restrict__ bl,
    const float* __restrict__ Wr, float* __restrict__ out)
{
    __shared__ float sWl[HDIM * CDIM], sWr[HDIM * CDIM], sb[CDIM];
    __shared__ float sm[8][HDIM], sh[8][HDIM];
    int tid = threadIdx.x;
    for (int i = tid; i < HDIM * CDIM; i += 256) { sWl[i] = Wl[i]; sWr[i] = Wr[i]; }
    if (tid < CDIM) sb[tid] = bl[tid];
    __syncthreads();

    int wid = tid >> 5, lane = tid & 31;
    int ntiles = NNODES / 8;
    for (int tile = blockIdx.x; tile < ntiles; tile += gridDim.x) {
        int n0 = tile * 8;
        for (int i = tid; i < 8 * HDIM; i += 256) {
            int rr = i >> 6, k = i & 63;
            sm[rr][k] = g_mean[(size_t)(n0 + rr) * HDIM + k];
            sh[rr][k] = g_h  [(size_t)(n0 + rr) * HDIM + k];
        }
        __syncthreads();
        int c = (lane < CDIM) ? lane : 0;
        float acc = sb[c];
        #pragma unroll
        for (int k = 0; k < HDIM; k++)
            acc += sm[wid][k] * sWl[k * CDIM + c] + sh[wid][k] * sWr[k * CDIM + c];
        float sq = (lane < CDIM) ? acc * acc : 0.f;
        #pragma unroll
        for (int d = 16; d; d >>= 1) sq += __shfl_xor_sync(0xffffffffu, sq, d);
        float scale = 1.f / fmaxf(sqrtf(sq), 1e-12f);
        if (lane < CDIM) out[(size_t)(n0 + wid) * CDIM + lane] = acc * scale;
        __syncthreads();
    }
}

// ---------------- launch ------------------------------------------------------
extern "C" void kernel_launch(void* const* d_in, const int* in_sizes, int n_in,
                              void* d_out, int out_size)
{
    const float* x    = (const float*)d_in[0];
    const int*   ei   = (const int*)d_in[1];     // int32 (JAX x64 disabled)
    const float* ew   = (const float*)d_in[2];
    const float* embW = (const float*)d_in[3];
    const float* embB = (const float*)d_in[4];
    const float* Wl1  = (const float*)d_in[5];
    const float* bl1  = (const float*)d_in[6];
    const float* Wr1  = (const float*)d_in[7];
    const float* Wl2  = (const float*)d_in[8];
    const float* bl2  = (const float*)d_in[9];
    const float* Wr2  = (const float*)d_in[10];
    const float* Wl3  = (const float*)d_in[11];
    const float* bl3  = (const float*)d_in[12];
    const float* Wr3  = (const float*)d_in[13];
    const float* Wl4  = (const float*)d_in[14];
    const float* bl4  = (const float*)d_in[15];
    const float* Wr4  = (const float*)d_in[16];
    float* out = (float*)d_out;

    // CSR build (amortized over 4 conv layers)
    zero_deg_kernel<<<(NNODES + 255) / 256, 256>>>();
    hist_kernel<<<2048, 256>>>(ei);
    scan_kernel<<<1, 1024>>>();
    scatter_kernel<<<2048, 256>>>(ei, ew);

    // embedding
    embed_kernel<<<1184, 256>>>(x, embW, embB);

    const int AGG_GRID = (NNODES * 32 + 255) / 256;  // one warp per node

    // layer 1..3 (weighted aggregation)
    aggregate_kernel<<<AGG_GRID, 256>>>(1);
    sage_mid_kernel<<<1184, 256>>>(Wl1, bl1, Wr1);
    aggregate_kernel<<<AGG_GRID, 256>>>(1);
    sage_mid_kernel<<<1184, 256>>>(Wl2, bl2, Wr2);
    aggregate_kernel<<<AGG_GRID, 256>>>(1);
    sage_mid_kernel<<<1184, 256>>>(Wl3, bl3, Wr3);

    // layer 4 (unweighted aggregation, C=18 output, no relu)
    aggregate_kernel<<<AGG_GRID, 256>>>(0);
    sage_final_kernel<<<1184, 256>>>(Wl4, bl4, Wr4, out);
}

// round 3
// speedup vs baseline: 1.6828x; 1.6828x over previous
#include <cuda_runtime.h>
#include <cuda_fp16.h>
#include <cstdint>

#define NNODES 100000
#define NEDGES 3200000
#define HDIM   64
#define FIN    100
#define CDIM   18
#define NTILES 3125    // NNODES / 32

// ---------------- scratch (device globals — no allocation allowed) ----------
__device__ float g_h[(size_t)NNODES * HDIM];      // node features (fp32)
__device__ uint4 g_hh[(size_t)NNODES * 8];        // node features (fp16, 128B/row)
__device__ float g_mean[(size_t)NNODES * HDIM];   // aggregated neighbor mean
__device__ int   g_deg[NNODES];
__device__ int   g_off[NNODES + 1];
__device__ int   g_cur[NNODES];
__device__ int   g_src[NEDGES];
__device__ float g_w[NEDGES];

__device__ __forceinline__ int clampi(int v, int lo, int hi) {
    return v < lo ? lo : (v > hi ? hi : v);
}

__device__ __forceinline__ void store_row_f32_f16(int node, int c0, float4 o) {
    *(float4*)(g_h + (size_t)node * HDIM + c0) = o;
    __half2 p0 = __floats2half2_rn(o.x, o.y);
    __half2 p1 = __floats2half2_rn(o.z, o.w);
    uint2 u;
    u.x = *(unsigned*)&p0;
    u.y = *(unsigned*)&p1;
    *(uint2*)((__half*)g_hh + (size_t)node * HDIM + c0) = u;
}

// ---------------- embedding: h = relu(x @ W + b) ----------------------------
// 128 threads, 32-node tiles, 4x4 register blocking, k unrolled x4
__global__ __launch_bounds__(128) void embed_kernel(
    const float* __restrict__ x, const float* __restrict__ W,
    const float* __restrict__ b)
{
    __shared__ float sW[FIN * HDIM];     // 25.6 KB, k-major
    __shared__ float sx[32 * FIN];       // 12.8 KB
    int tid = threadIdx.x;
    int rg = tid >> 4, cg = tid & 15;
    int c0 = cg * 4;
    float bias[4];
    #pragma unroll
    for (int j = 0; j < 4; j++) bias[j] = b[c0 + j];
    for (int i = tid; i < FIN * HDIM; i += 128) sW[i] = W[i];
    __syncthreads();

    for (int tile = blockIdx.x; tile < NTILES; tile += gridDim.x) {
        int n0 = tile * 32;
        const float4* gx4 = (const float4*)(x + (size_t)n0 * FIN);
        float4* sx4 = (float4*)sx;
        for (int i = tid; i < 32 * 25; i += 128) sx4[i] = gx4[i];
        __syncthreads();

        float acc[4][4];
        #pragma unroll
        for (int j = 0; j < 4; j++)
            #pragma unroll
            for (int jj = 0; jj < 4; jj++) acc[j][jj] = bias[jj];

        int r0 = rg * 4;
        #pragma unroll 5
        for (int k = 0; k < FIN; k += 4) {
            float4 w0 = *(const float4*)&sW[(k + 0) * HDIM + c0];
            float4 w1 = *(const float4*)&sW[(k + 1) * HDIM + c0];
            float4 w2 = *(const float4*)&sW[(k + 2) * HDIM + c0];
            float4 w3 = *(const float4*)&sW[(k + 3) * HDIM + c0];
            #pragma unroll
            for (int j = 0; j < 4; j++) {
                float4 xv = *(const float4*)&sx[(r0 + j) * FIN + k];
                acc[j][0] += xv.x * w0.x + xv.y * w1.x + xv.z * w2.x + xv.w * w3.x;
                acc[j][1] += xv.x * w0.y + xv.y * w1.y + xv.z * w2.y + xv.w * w3.y;
                acc[j][2] += xv.x * w0.z + xv.y * w1.z + xv.z * w2.z + xv.w * w3.z;
                acc[j][3] += xv.x * w0.w + xv.y * w1.w + xv.z * w2.w + xv.w * w3.w;
            }
        }
        #pragma unroll
        for (int j = 0; j < 4; j++) {
            float4 o;
            o.x = fmaxf(acc[j][0], 0.f); o.y = fmaxf(acc[j][1], 0.f);
            o.z = fmaxf(acc[j][2], 0.f); o.w = fmaxf(acc[j][3], 0.f);
            store_row_f32_f16(n0 + r0 + j, c0, o);
        }
        __syncthreads();
    }
}

// ---------------- CSR build ---------------------------------------------------
__global__ void zero_deg_kernel() {
    int i = blockIdx.x * blockDim.x + threadIdx.x;
    if (i < NNODES) g_deg[i] = 0;
}

__global__ void hist_kernel(const int* __restrict__ ei) {
    int stride = gridDim.x * blockDim.x;
    for (int e = blockIdx.x * blockDim.x + threadIdx.x; e < NEDGES; e += stride) {
        int d = clampi(ei[NEDGES + e], 0, NNODES - 1);
        atomicAdd(&g_deg[d], 1);
    }
}

__global__ __launch_bounds__(1024) void scan_kernel() {
    __shared__ int wsum[32];
    int tid = threadIdx.x, lane = tid & 31, wid = tid >> 5;
    int carry = 0;
    for (int base = 0; base < NNODES; base += 1024) {
        int i = base + tid;
        int v = (i < NNODES) ? g_deg[i] : 0;
        int xval = v;
        #pragma unroll
        for (int d = 1; d < 32; d <<= 1) {
            int y = __shfl_up_sync(0xffffffffu, xval, d);
            if (lane >= d) xval += y;
        }
        if (lane == 31) wsum[wid] = xval;
        __syncthreads();
        if (wid == 0) {
            int s = wsum[lane];
            #pragma unroll
            for (int d = 1; d < 32; d <<= 1) {
                int y = __shfl_up_sync(0xffffffffu, s, d);
                if (lane >= d) s += y;
            }
            wsum[lane] = s;
        }
        __syncthreads();
        int excl = carry + (wid ? wsum[wid - 1] : 0) + (xval - v);
        if (i < NNODES) { g_off[i] = excl; g_cur[i] = excl; }
        int total = wsum[31];
        __syncthreads();
        carry += total;
    }
    if (tid == 0) g_off[NNODES] = carry;
}

__global__ void scatter_kernel(const int* __restrict__ ei,
                               const float* __restrict__ ew)
{
    int stride = gridDim.x * blockDim.x;
    for (int e = blockIdx.x * blockDim.x + threadIdx.x; e < NEDGES; e += stride) {
        int s = clampi(ei[e], 0, NNODES - 1);
        int d = clampi(ei[NEDGES + e], 0, NNODES - 1);
        int pos = atomicAdd(&g_cur[d], 1);
        if (pos >= 0 && pos < NEDGES) {
            g_src[pos] = s;
            g_w[pos]   = ew[e];
        }
    }
}

// ---------------- aggregation: warp per node, fp16 gather, 4 edges / round --
__global__ __launch_bounds__(256) void aggregate_kernel(int useW) {
    int node = (blockIdx.x * blockDim.x + threadIdx.x) >> 5;
    if (node >= NNODES) return;
    int lane = threadIdx.x & 31;
    int sub = lane & 7;     // uint4 index within 128B row (channels sub*8..sub*8+7)
    int grp = lane >> 3;    // which of 4 edges this round

    int s = g_off[node], e = g_off[node + 1];
    float acc[8];
    #pragma unroll
    for (int j = 0; j < 8; j++) acc[j] = 0.f;

    for (int i = s; i < e; i += 4) {
        int eidx = i + grp;
        bool pred = eidx < e;
        int src = pred ? g_src[eidx] : 0;
        float w = useW ? (pred ? g_w[eidx] : 0.f) : (pred ? 1.f : 0.f);
        uint4 v = g_hh[(size_t)src * 8 + sub];
        const __half2* hp = (const __half2*)&v;
        #pragma unroll
        for (int t = 0; t < 4; t++) {
            float2 f = __half22float2(hp[t]);
            acc[2 * t]     += w * f.x;
            acc[2 * t + 1] += w * f.y;
        }
    }
    // combine the 4 edge-groups (lanes xor 8, xor 16)
    #pragma unroll
    for (int j = 0; j < 8; j++) {
        acc[j] += __shfl_xor_sync(0xffffffffu, acc[j], 8);
        acc[j] += __shfl_xor_sync(0xffffffffu, acc[j], 16);
    }
    float inv = 1.f / fmaxf((float)(e - s), 1.f);
    if (lane < 8) {
        float4 o0 = make_float4(acc[0] * inv, acc[1] * inv, acc[2] * inv, acc[3] * inv);
        float4 o1 = make_float4(acc[4] * inv, acc[5] * inv, acc[6] * inv, acc[7] * inv);
        float4* m4 = (float4*)(g_mean + (size_t)node * HDIM) + sub * 2;
        m4[0] = o0;
        m4[1] = o1;
    }
}

// ---------------- middle layers: h = relu(normalize(mean@Wl + bl + h@Wr)) ----
// 128 threads, 32-node tiles, 4x4 register blocking, k unrolled x4
__global__ __launch_bounds__(128) void sage_mid_kernel(
    const float* __restrict__ Wl, const float* __restrict__ bl,
    const float* __restrict__ Wr)
{
    __shared__ float sWl[HDIM * HDIM], sWr[HDIM * HDIM];   // 32 KB
    __shared__ float sm[32 * HDIM], sh[32 * HDIM];         // 16 KB
    int tid = threadIdx.x;
    int rg = tid >> 4, cg = tid & 15;
    int c0 = cg * 4;
    float bias[4];
    #pragma unroll
    for (int j = 0; j < 4; j++) bias[j] = bl[c0 + j];
    for (int i = tid; i < HDIM * HDIM; i += 128) { sWl[i] = Wl[i]; sWr[i] = Wr[i]; }
    __syncthreads();

    for (int tile = blockIdx.x; tile < NTILES; tile += gridDim.x) {
        int n0 = tile * 32;
        {
            const float4* gm4 = (const float4*)(g_mean + (size_t)n0 * HDIM);
            const float4* gh4 = (const float4*)(g_h   + (size_t)n0 * HDIM);
            float4* sm4 = (float4*)sm;
            float4* sh4 = (float4*)sh;
            for (int i = tid; i < 512; i += 128) { sm4[i] = gm4[i]; sh4[i] = gh4[i]; }
        }
        __syncthreads();

        float acc[4][4];
        #pragma unroll
        for (int j = 0; j < 4; j++)
            #pragma unroll
            for (int jj = 0; jj < 4; jj++) acc[j][jj] = bias[jj];

        int r0 = rg * 4;
        #pragma unroll 4
        for (int k = 0; k < HDIM; k += 4) {
            float4 l0 = *(const float4*)&sWl[(k + 0) * HDIM + c0];
            float4 l1 = *(const float4*)&sWl[(k + 1) * HDIM + c0];
            float4 l2 = *(const float4*)&sWl[(k + 2) * HDIM + c0];
            float4 l3 = *(const float4*)&sWl[(k + 3) * HDIM + c0];
            float4 q0 = *(const float4*)&sWr[(k + 0) * HDIM + c0];
            float4 q1 = *(const float4*)&sWr[(k + 1) * HDIM + c0];
            float4 q2 = *(const float4*)&sWr[(k + 2) * HDIM + c0];
            float4 q3 = *(const float4*)&sWr[(k + 3) * HDIM + c0];
            #pragma unroll
            for (int j = 0; j < 4; j++) {
                float4 mv = *(const float4*)&sm[(r0 + j) * HDIM + k];
                float4 hv = *(const float4*)&sh[(r0 + j) * HDIM + k];
                acc[j][0] += mv.x * l0.x + mv.y * l1.x + mv.z * l2.x + mv.w * l3.x
                           + hv.x * q0.x + hv.y * q1.x + hv.z * q2.x + hv.w * q3.x;
                acc[j][1] += mv.x * l0.y + mv.y * l1.y + mv.z * l2.y + mv.w * l3.y
                           + hv.x * q0.y + hv.y * q1.y + hv.z * q2.y + hv.w * q3.y;
                acc[j][2] += mv.x * l0.z + mv.y * l1.z + mv.z * l2.z + mv.w * l3.z
                           + hv.x * q0.z + hv.y * q1.z + hv.z * q2.z + hv.w * q3.z;
                acc[j][3] += mv.x * l0.w + mv.y * l1.w + mv.z * l2.w + mv.w * l3.w
                           + hv.x * q0.w + hv.y * q1.w + hv.z * q2.w + hv.w * q3.w;
            }
        }
        // L2-normalize each row (sum over 16 cg groups via shfl butterfly),
        // relu, store fp32 + fp16
        #pragma unroll
        for (int j = 0; j < 4; j++) {
            float sq = acc[j][0] * acc[j][0] + acc[j][1] * acc[j][1]
                     + acc[j][2] * acc[j][2] + acc[j][3] * acc[j][3];
            #pragma unroll
            for (int d = 1; d < 16; d <<= 1)
                sq += __shfl_xor_sync(0xffffffffu, sq, d);
            float scale = 1.f / fmaxf(sqrtf(sq), 1e-12f);
            float4 o;
            o.x = fmaxf(acc[j][0] * scale, 0.f);
            o.y = fmaxf(acc[j][1] * scale, 0.f);
            o.z = fmaxf(acc[j][2] * scale, 0.f);
            o.w = fmaxf(acc[j][3] * scale, 0.f);
            store_row_f32_f16(n0 + r0 + j, c0, o);
        }
        __syncthreads();
    }
}

// ---------------- final layer: out = normalize(mean@Wl4 + bl4 + h@Wr4) -------
__global__ __launch_bounds__(256) void sage_final_kernel(
    const float* __restrict__ Wl, const float* __restrict__ bl,
    const float* __restrict__ Wr, float* __restrict__ out)
{
    __shared__ float sWl[HDIM * CDIM], sWr[HDIM * CDIM], sb[CDIM];
    __shared__ float sm[8][HDIM], sh[8][HDIM];
    int tid = threadIdx.x;
    for (int i = tid; i < HDIM * CDIM; i += 256) { sWl[i] = Wl[i]; sWr[i] = Wr[i]; }
    if (tid < CDIM) sb[tid] = bl[tid];
    __syncthreads();

    int wid = tid >> 5, lane = tid & 31;
    int ntiles = NNODES / 8;
    for (int tile = blockIdx.x; tile < ntiles; tile += gridDim.x) {
        int n0 = tile * 8;
        for (int i = tid; i < 8 * HDIM; i += 256) {
            int rr = i >> 6, k = i & 63;
            sm[rr][k] = g_mean[(size_t)(n0 + rr) * HDIM + k];
            sh[rr][k] = g_h  [(size_t)(n0 + rr) * HDIM + k];
        }
        __syncthreads();
        int c = (lane < CDIM) ? lane : 0;
        float acc = sb[c];
        #pragma unroll
        for (int k = 0; k < HDIM; k++)
            acc += sm[wid][k] * sWl[k * CDIM + c] + sh[wid][k] * sWr[k * CDIM + c];
        float sq = (lane < CDIM) ? acc * acc : 0.f;
        #pragma unroll
        for (int d = 16; d; d >>= 1) sq += __shfl_xor_sync(0xffffffffu, sq, d);
        float scale = 1.f / fmaxf(sqrtf(sq), 1e-12f);
        if (lane < CDIM) out[(size_t)(n0 + wid) * CDIM + lane] = acc * scale;
        __syncthreads();
    }
}

// ---------------- launch ------------------------------------------------------
extern "C" void kernel_launch(void* const* d_in, const int* in_sizes, int n_in,
                              void* d_out, int out_size)
{
    const float* x    = (const float*)d_in[0];
    const int*   ei   = (const int*)d_in[1];     // int32 (JAX x64 disabled)
    const float* ew   = (const float*)d_in[2];
    const float* embW = (const float*)d_in[3];
    const float* embB = (const float*)d_in[4];
    const float* Wl1  = (const float*)d_in[5];
    const float* bl1  = (const float*)d_in[6];
    const float* Wr1  = (const float*)d_in[7];
    const float* Wl2  = (const float*)d_in[8];
    const float* bl2  = (const float*)d_in[9];
    const float* Wr2  = (const float*)d_in[10];
    const float* Wl3  = (const float*)d_in[11];
    const float* bl3  = (const float*)d_in[12];
    const float* Wr3  = (const float*)d_in[13];
    const float* Wl4  = (const float*)d_in[14];
    const float* bl4  = (const float*)d_in[15];
    const float* Wr4  = (const float*)d_in[16];
    float* out = (float*)d_out;

    // CSR build (amortized over 4 conv layers)
    zero_deg_kernel<<<(NNODES + 255) / 256, 256>>>();
    hist_kernel<<<2048, 256>>>(ei);
    scan_kernel<<<1, 1024>>>();
    scatter_kernel<<<2048, 256>>>(ei, ew);

    // embedding
    embed_kernel<<<740, 128>>>(x, embW, embB);

    const int AGG_GRID = NNODES / 8;   // 8 warps per block, one warp per node

    aggregate_kernel<<<AGG_GRID, 256>>>(1);
    sage_mid_kernel<<<592, 128>>>(Wl1, bl1, Wr1);
    aggregate_kernel<<<AGG_GRID, 256>>>(1);
    sage_mid_kernel<<<592, 128>>>(Wl2, bl2, Wr2);
    aggregate_kernel<<<AGG_GRID, 256>>>(1);
    sage_mid_kernel<<<592, 128>>>(Wl3, bl3, Wr3);

    aggregate_kernel<<<AGG_GRID, 256>>>(0);
    sage_final_kernel<<<1184, 256>>>(Wl4, bl4, Wr4, out);
}

// round 4
// speedup vs baseline: 1.9382x; 1.1518x over previous
#include <cuda_runtime.h>
#include <cuda_fp16.h>
#include <cstdint>

#define NNODES 100000
#define NEDGES 3200000
#define HDIM   64
#define FIN    100
#define CDIM   18
#define NTILES 3125    // NNODES / 32
#define SCAN_B 98      // ceil(NNODES / 1024)

// ---------------- scratch (device globals — no allocation allowed) ----------
__device__ float g_h[(size_t)NNODES * HDIM];      // node features (fp32)
__device__ uint4 g_hh[(size_t)NNODES * 8];        // node features (fp16, 128B/row)
__device__ float g_mean[(size_t)NNODES * HDIM];   // aggregated neighbor mean
__device__ int   g_deg[NNODES];
__device__ int   g_off[NNODES + 1];
__device__ int   g_cur[NNODES];
__device__ int   g_bsum[SCAN_B];
__device__ int2  g_edge[NEDGES];                  // packed (src, weight bits)

__device__ __forceinline__ int clampi(int v, int lo, int hi) {
    return v < lo ? lo : (v > hi ? hi : v);
}

__device__ __forceinline__ void store_row_f32_f16(int node, int c0, float4 o) {
    *(float4*)(g_h + (size_t)node * HDIM + c0) = o;
    __half2 p0 = __floats2half2_rn(o.x, o.y);
    __half2 p1 = __floats2half2_rn(o.z, o.w);
    uint2 u;
    u.x = *(unsigned*)&p0;
    u.y = *(unsigned*)&p1;
    *(uint2*)((__half*)g_hh + (size_t)node * HDIM + c0) = u;
}

// ---------------- embedding: h = relu(x @ W + b) ----------------------------
__global__ __launch_bounds__(128) void embed_kernel(
    const float* __restrict__ x, const float* __restrict__ W,
    const float* __restrict__ b)
{
    __shared__ float sW[FIN * HDIM];     // 25.6 KB, k-major
    __shared__ float sx[32 * FIN];       // 12.8 KB
    int tid = threadIdx.x;
    int rg = tid >> 4, cg = tid & 15;
    int c0 = cg * 4;
    float bias[4];
    #pragma unroll
    for (int j = 0; j < 4; j++) bias[j] = b[c0 + j];
    for (int i = tid; i < FIN * HDIM; i += 128) sW[i] = W[i];
    __syncthreads();

    for (int tile = blockIdx.x; tile < NTILES; tile += gridDim.x) {
        int n0 = tile * 32;
        const float4* gx4 = (const float4*)(x + (size_t)n0 * FIN);
        float4* sx4 = (float4*)sx;
        for (int i = tid; i < 32 * 25; i += 128) sx4[i] = gx4[i];
        __syncthreads();

        float acc[4][4];
        #pragma unroll
        for (int j = 0; j < 4; j++)
            #pragma unroll
            for (int jj = 0; jj < 4; jj++) acc[j][jj] = bias[jj];

        int r0 = rg * 4;
        #pragma unroll 5
        for (int k = 0; k < FIN; k += 4) {
            float4 w0 = *(const float4*)&sW[(k + 0) * HDIM + c0];
            float4 w1 = *(const float4*)&sW[(k + 1) * HDIM + c0];
            float4 w2 = *(const float4*)&sW[(k + 2) * HDIM + c0];
            float4 w3 = *(const float4*)&sW[(k + 3) * HDIM + c0];
            #pragma unroll
            for (int j = 0; j < 4; j++) {
                float4 xv = *(const float4*)&sx[(r0 + j) * FIN + k];
                acc[j][0] += xv.x * w0.x + xv.y * w1.x + xv.z * w2.x + xv.w * w3.x;
                acc[j][1] += xv.x * w0.y + xv.y * w1.y + xv.z * w2.y + xv.w * w3.y;
                acc[j][2] += xv.x * w0.z + xv.y * w1.z + xv.z * w2.z + xv.w * w3.z;
                acc[j][3] += xv.x * w0.w + xv.y * w1.w + xv.z * w2.w + xv.w * w3.w;
            }
        }
        #pragma unroll
        for (int j = 0; j < 4; j++) {
            float4 o;
            o.x = fmaxf(acc[j][0], 0.f); o.y = fmaxf(acc[j][1], 0.f);
            o.z = fmaxf(acc[j][2], 0.f); o.w = fmaxf(acc[j][3], 0.f);
            store_row_f32_f16(n0 + r0 + j, c0, o);
        }
        __syncthreads();
    }
}

// ---------------- CSR build ---------------------------------------------------
__global__ void zero_deg_kernel() {
    int i = blockIdx.x * blockDim.x + threadIdx.x;
    if (i < NNODES) g_deg[i] = 0;
}

// vectorized histogram: int4 loads of dst, 4 REDG per thread-iter
__global__ void hist_kernel(const int* __restrict__ ei) {
    int t = blockIdx.x * blockDim.x + threadIdx.x;
    int stride = gridDim.x * blockDim.x;
    const int4* dst4 = (const int4*)(ei + NEDGES);
    for (int e = t; e < NEDGES / 4; e += stride) {
        int4 d = dst4[e];
        atomicAdd(&g_deg[clampi(d.x, 0, NNODES - 1)], 1);
        atomicAdd(&g_deg[clampi(d.y, 0, NNODES - 1)], 1);
        atomicAdd(&g_deg[clampi(d.z, 0, NNODES - 1)], 1);
        atomicAdd(&g_deg[clampi(d.w, 0, NNODES - 1)], 1);
    }
}

// multi-block scan, phase 1: per-block local exclusive scan + block total
__global__ __launch_bounds__(1024) void scan1_kernel() {
    __shared__ int wsum[32];
    int tid = threadIdx.x, lane = tid & 31, wid = tid >> 5;
    int i = blockIdx.x * 1024 + tid;
    int v = (i < NNODES) ? g_deg[i] : 0;
    int xval = v;
    #pragma unroll
    for (int d = 1; d < 32; d <<= 1) {
        int y = __shfl_up_sync(0xffffffffu, xval, d);
        if (lane >= d) xval += y;
    }
    if (lane == 31) wsum[wid] = xval;
    __syncthreads();
    if (wid == 0) {
        int s = wsum[lane];
        #pragma unroll
        for (int d = 1; d < 32; d <<= 1) {
            int y = __shfl_up_sync(0xffffffffu, s, d);
            if (lane >= d) s += y;
        }
        wsum[lane] = s;
    }
    __syncthreads();
    int excl = (wid ? wsum[wid - 1] : 0) + (xval - v);
    if (i < NNODES) g_off[i] = excl;
    if (tid == 0) g_bsum[blockIdx.x] = wsum[31];
}

// phase 2: single warp scans block totals
__global__ void scan2_kernel() {
    int lane = threadIdx.x;
    int carry = 0;
    for (int base = 0; base < SCAN_B; base += 32) {
        int i = base + lane;
        int v = (i < SCAN_B) ? g_bsum[i] : 0;
        int xval = v;
        #pragma unroll
        for (int d = 1; d < 32; d <<= 1) {
            int y = __shfl_up_sync(0xffffffffu, xval, d);
            if (lane >= d) xval += y;
        }
        if (i < SCAN_B) g_bsum[i] = carry + xval - v;
        carry += __shfl_sync(0xffffffffu, xval, 31);
    }
    if (lane == 0) g_off[NNODES] = carry;
}

// phase 3: add block prefix, init cursors
__global__ void scan3_kernel() {
    int i = blockIdx.x * blockDim.x + threadIdx.x;
    if (i < NNODES) {
        int v = g_off[i] + g_bsum[i >> 10];
        g_off[i] = v;
        g_cur[i] = v;
    }
}

__global__ void scatter_kernel(const int* __restrict__ ei,
                               const float* __restrict__ ew)
{
    int stride = gridDim.x * blockDim.x;
    for (int e = blockIdx.x * blockDim.x + threadIdx.x; e < NEDGES; e += stride) {
        int s = clampi(ei[e], 0, NNODES - 1);
        int d = clampi(ei[NEDGES + e], 0, NNODES - 1);
        int pos = atomicAdd(&g_cur[d], 1);
        if (pos >= 0 && pos < NEDGES)
            g_edge[pos] = make_int2(s, __float_as_int(ew[e]));   // single 8B store
    }
}

// ---------------- aggregation: warp per node, fp16 gather, 8 edges in flight -
__global__ __launch_bounds__(256) void aggregate_kernel(int useW) {
    int node = (blockIdx.x * blockDim.x + threadIdx.x) >> 5;
    if (node >= NNODES) return;
    int lane = threadIdx.x & 31;
    int sub = lane & 7;     // uint4 index within 128B row
    int grp = lane >> 3;    // which of 4 edges per slot

    int s = g_off[node], e = g_off[node + 1];
    float acc[8];
    #pragma unroll
    for (int j = 0; j < 8; j++) acc[j] = 0.f;

    int i = s + grp;
    // two independent gather chains per iteration
    for (; i + 4 < e; i += 8) {
        int2 p0 = g_edge[i];
        int2 p1 = g_edge[i + 4];
        float w0 = useW ? __int_as_float(p0.y) : 1.f;
        float w1 = useW ? __int_as_float(p1.y) : 1.f;
        uint4 v0 = g_hh[(size_t)p0.x * 8 + sub];
        uint4 v1 = g_hh[(size_t)p1.x * 8 + sub];
        const __half2* h0 = (const __half2*)&v0;
        const __half2* h1 = (const __half2*)&v1;
        #pragma unroll
        for (int t = 0; t < 4; t++) {
            float2 f0 = __half22float2(h0[t]);
            float2 f1 = __half22float2(h1[t]);
            acc[2 * t]     += w0 * f0.x + w1 * f1.x;
            acc[2 * t + 1] += w0 * f0.y + w1 * f1.y;
        }
    }
    if (i < e) {
        int2 p0 = g_edge[i];
        float w0 = useW ? __int_as_float(p0.y) : 1.f;
        uint4 v0 = g_hh[(size_t)p0.x * 8 + sub];
        const __half2* h0 = (const __half2*)&v0;
        #pragma unroll
        for (int t = 0; t < 4; t++) {
            float2 f0 = __half22float2(h0[t]);
            acc[2 * t]     += w0 * f0.x;
            acc[2 * t + 1] += w0 * f0.y;
        }
    }
    // combine the 4 edge-groups (lanes xor 8, xor 16)
    #pragma unroll
    for (int j = 0; j < 8; j++) {
        acc[j] += __shfl_xor_sync(0xffffffffu, acc[j], 8);
        acc[j] += __shfl_xor_sync(0xffffffffu, acc[j], 16);
    }
    float inv = 1.f / fmaxf((float)(e - s), 1.f);
    if (lane < 8) {
        float4 o0 = make_float4(acc[0] * inv, acc[1] * inv, acc[2] * inv, acc[3] * inv);
        float4 o1 = make_float4(acc[4] * inv, acc[5] * inv, acc[6] * inv, acc[7] * inv);
        float4* m4 = (float4*)(g_mean + (size_t)node * HDIM) + sub * 2;
        m4[0] = o0;
        m4[1] = o1;
    }
}

// ---------------- middle layers: h = relu(normalize(mean@Wl + bl + h@Wr)) ----
__global__ __launch_bounds__(128) void sage_mid_kernel(
    const float* __restrict__ Wl, const float* __restrict__ bl,
    const float* __restrict__ Wr)
{
    __shared__ float sWl[HDIM * HDIM], sWr[HDIM * HDIM];   // 32 KB
    __shared__ float sm[32 * HDIM], sh[32 * HDIM];         // 16 KB
    int tid = threadIdx.x;
    int rg = tid >> 4, cg = tid & 15;
    int c0 = cg * 4;
    float bias[4];
    #pragma unroll
    for (int j = 0; j < 4; j++) bias[j] = bl[c0 + j];
    for (int i = tid; i < HDIM * HDIM; i += 128) { sWl[i] = Wl[i]; sWr[i] = Wr[i]; }
    __syncthreads();

    for (int tile = blockIdx.x; tile < NTILES; tile += gridDim.x) {
        int n0 = tile * 32;
        {
            const float4* gm4 = (const float4*)(g_mean + (size_t)n0 * HDIM);
            const float4* gh4 = (const float4*)(g_h   + (size_t)n0 * HDIM);
            float4* sm4 = (float4*)sm;
            float4* sh4 = (float4*)sh;
            for (int i = tid; i < 512; i += 128) { sm4[i] = gm4[i]; sh4[i] = gh4[i]; }
        }
        __syncthreads();

        float acc[4][4];
        #pragma unroll
        for (int j = 0; j < 4; j++)
            #pragma unroll
            for (int jj = 0; jj < 4; jj++) acc[j][jj] = bias[jj];

        int r0 = rg * 4;
        #pragma unroll 4
        for (int k = 0; k < HDIM; k += 4) {
            float4 l0 = *(const float4*)&sWl[(k + 0) * HDIM + c0];
            float4 l1 = *(const float4*)&sWl[(k + 1) * HDIM + c0];
            float4 l2 = *(const float4*)&sWl[(k + 2) * HDIM + c0];
            float4 l3 = *(const float4*)&sWl[(k + 3) * HDIM + c0];
            float4 q0 = *(const float4*)&sWr[(k + 0) * HDIM + c0];
            float4 q1 = *(const float4*)&sWr[(k + 1) * HDIM + c0];
            float4 q2 = *(const float4*)&sWr[(k + 2) * HDIM + c0];
            float4 q3 = *(const float4*)&sWr[(k + 3) * HDIM + c0];
            #pragma unroll
            for (int j = 0; j < 4; j++) {
                float4 mv = *(const float4*)&sm[(r0 + j) * HDIM + k];
                float4 hv = *(const float4*)&sh[(r0 + j) * HDIM + k];
                acc[j][0] += mv.x * l0.x + mv.y * l1.x + mv.z * l2.x + mv.w * l3.x
                           + hv.x * q0.x + hv.y * q1.x + hv.z * q2.x + hv.w * q3.x;
                acc[j][1] += mv.x * l0.y + mv.y * l1.y + mv.z * l2.y + mv.w * l3.y
                           + hv.x * q0.y + hv.y * q1.y + hv.z * q2.y + hv.w * q3.y;
                acc[j][2] += mv.x * l0.z + mv.y * l1.z + mv.z * l2.z + mv.w * l3.z
                           + hv.x * q0.z + hv.y * q1.z + hv.z * q2.z + hv.w * q3.z;
                acc[j][3] += mv.x * l0.w + mv.y * l1.w + mv.z * l2.w + mv.w * l3.w
                           + hv.x * q0.w + hv.y * q1.w + hv.z * q2.w + hv.w * q3.w;
            }
        }
        #pragma unroll
        for (int j = 0; j < 4; j++) {
            float sq = acc[j][0] * acc[j][0] + acc[j][1] * acc[j][1]
                     + acc[j][2] * acc[j][2] + acc[j][3] * acc[j][3];
            #pragma unroll
            for (int d = 1; d < 16; d <<= 1)
                sq += __shfl_xor_sync(0xffffffffu, sq, d);
            float scale = 1.f / fmaxf(sqrtf(sq), 1e-12f);
            float4 o;
            o.x = fmaxf(acc[j][0] * scale, 0.f);
            o.y = fmaxf(acc[j][1] * scale, 0.f);
            o.z = fmaxf(acc[j][2] * scale, 0.f);
            o.w = fmaxf(acc[j][3] * scale, 0.f);
            store_row_f32_f16(n0 + r0 + j, c0, o);
        }
        __syncthreads();
    }
}

// ---------------- final layer: out = normalize(mean@Wl4 + bl4 + h@Wr4) -------
__global__ __launch_bounds__(256) void sage_final_kernel(
    const float* __restrict__ Wl, const float* __restrict__ bl,
    const float* __restrict__ Wr, float* __restrict__ out)
{
    __shared__ float sWl[HDIM * CDIM], sWr[HDIM * CDIM], sb[CDIM];
    __shared__ float sm[8][HDIM], sh[8][HDIM];
    int tid = threadIdx.x;
    for (int i = tid; i < HDIM * CDIM; i += 256) { sWl[i] = Wl[i]; sWr[i] = Wr[i]; }
    if (tid < CDIM) sb[tid] = bl[tid];
    __syncthreads();

    int wid = tid >> 5, lane = tid & 31;
    int ntiles = NNODES / 8;
    for (int tile = blockIdx.x; tile < ntiles; tile += gridDim.x) {
        int n0 = tile * 8;
        for (int i = tid; i < 8 * HDIM; i += 256) {
            int rr = i >> 6, k = i & 63;
            sm[rr][k] = g_mean[(size_t)(n0 + rr) * HDIM + k];
            sh[rr][k] = g_h  [(size_t)(n0 + rr) * HDIM + k];
        }
        __syncthreads();
        int c = (lane < CDIM) ? lane : 0;
        float acc = sb[c];
        #pragma unroll
        for (int k = 0; k < HDIM; k++)
            acc += sm[wid][k] * sWl[k * CDIM + c] + sh[wid][k] * sWr[k * CDIM + c];
        float sq = (lane < CDIM) ? acc * acc : 0.f;
        #pragma unroll
        for (int d = 16; d; d >>= 1) sq += __shfl_xor_sync(0xffffffffu, sq, d);
        float scale = 1.f / fmaxf(sqrtf(sq), 1e-12f);
        if (lane < CDIM) out[(size_t)(n0 + wid) * CDIM + lane] = acc * scale;
        __syncthreads();
    }
}

// ---------------- launch ------------------------------------------------------
extern "C" void kernel_launch(void* const* d_in, const int* in_sizes, int n_in,
                              void* d_out, int out_size)
{
    const float* x    = (const float*)d_in[0];
    const int*   ei   = (const int*)d_in[1];     // int32 (JAX x64 disabled)
    const float* ew   = (const float*)d_in[2];
    const float* embW = (const float*)d_in[3];
    const float* embB = (const float*)d_in[4];
    const float* Wl1  = (const float*)d_in[5];
    const float* bl1  = (const float*)d_in[6];
    const float* Wr1  = (const float*)d_in[7];
    const float* Wl2  = (const float*)d_in[8];
    const float* bl2  = (const float*)d_in[9];
    const float* Wr2  = (const float*)d_in[10];
    const float* Wl3  = (const float*)d_in[11];
    const float* bl3  = (const float*)d_in[12];
    const float* Wr3  = (const float*)d_in[13];
    const float* Wl4  = (const float*)d_in[14];
    const float* bl4  = (const float*)d_in[15];
    const float* Wr4  = (const float*)d_in[16];
    float* out = (float*)d_out;

    // CSR build
    zero_deg_kernel<<<(NNODES + 255) / 256, 256>>>();
    hist_kernel<<<1024, 256>>>(ei);
    scan1_kernel<<<SCAN_B, 1024>>>();
    scan2_kernel<<<1, 32>>>();
    scan3_kernel<<<(NNODES + 255) / 256, 256>>>();
    scatter_kernel<<<2048, 256>>>(ei, ew);

    // embedding
    embed_kernel<<<740, 128>>>(x, embW, embB);

    const int AGG_GRID = NNODES / 8;   // 8 warps per block, one warp per node

    aggregate_kernel<<<AGG_GRID, 256>>>(1);
    sage_mid_kernel<<<592, 128>>>(Wl1, bl1, Wr1);
    aggregate_kernel<<<AGG_GRID, 256>>>(1);
    sage_mid_kernel<<<592, 128>>>(Wl2, bl2, Wr2);
    aggregate_kernel<<<AGG_GRID, 256>>>(1);
    sage_mid_kernel<<<592, 128>>>(Wl3, bl3, Wr3);

    aggregate_kernel<<<AGG_GRID, 256>>>(0);
    sage_final_kernel<<<1184, 256>>>(Wl4, bl4, Wr4, out);
}